// round 16
// baseline (speedup 1.0000x reference)
#include <cuda_runtime.h>
#include <cuda_fp16.h>
#include <cuda_bf16.h>
#include <mma.h>
#include <cstdint>

using namespace nvcuda;

// Problem constants (fixed by the reference)
#define MAXN 50000
#define DIMV 128
#define HEADS 4
#define CH 32
#define MAXE 800000
#define LRELU_SLOPE 0.2f
#define LN_EPS 1e-5f

typedef unsigned long long ull;

// ---------------- scratch (device globals; no allocation allowed) ----------------
// g_hb layout (interleaved): [N][128] words, word = 2 bf16.
// For channel-pair p (0..63), layer l: word = (p>>1)*4 + l*2 + (p&1)
// => lane's uint4 at word lane*4 = {h1 pairs 2lane,2lane+1, h2 pairs 2lane,2lane+1}
__device__ unsigned int g_hb[MAXN * 128];
__device__ half  g_wh[2 * DIMV * DIMV];     // W1|W2 pre-converted to half, row-major [k][n]
__device__ float g_srcv[MAXN * 8];          // [node][head][layer]
__device__ float g_dstv[MAXN * 8];          // same layout
__device__ int   g_deg[MAXN];               // edge in-degree (zero-init; self-loop via +1)
__device__ int   g_off[MAXN + 1];           // CSR offsets
__device__ int   g_cursor[MAXN];            // scatter cursors
__device__ int   g_csr[MAXE + MAXN + 64];   // CSR src indices (grouped by dst) + pad
__device__ int   g_bsum[256];               // per-block degree sums

__device__ __forceinline__ float lrelu(float v) { return v > 0.f ? v : LRELU_SLOPE * v; }

__device__ __forceinline__ ull pack2(float x, float y) {
    ull r;
    asm("mov.b64 %0, {%1, %2};" : "=l"(r) : "f"(x), "f"(y));
    return r;
}
__device__ __forceinline__ void unpack2(ull v, float& x, float& y) {
    asm("mov.b64 {%0, %1}, %2;" : "=f"(x), "=f"(y) : "l"(v));
}
__device__ __forceinline__ void ffma2(ull& d, ull a, ull b) {
    asm("fma.rn.f32x2 %0, %1, %2, %0;" : "+l"(d) : "l"(a), "l"(b));
}
__device__ __forceinline__ unsigned int f2bf2(float lo, float hi) {
    unsigned int r;
    asm("cvt.rn.bf16x2.f32 %0, %1, %2;" : "=r"(r) : "f"(hi), "f"(lo));
    return r;
}
// word of two bf16 -> packed f32x2 (exact: bf16->f32 is <<16)
__device__ __forceinline__ ull bf2f2(unsigned int w) {
    ull r;
    asm("mov.b64 %0, {%1, %2};" : "=l"(r) : "r"(w << 16), "r"(w & 0xffff0000u));
    return r;
}

// ---------------- kernel 0: pre-convert W1|W2 to half ----------------
__global__ void wconv_kernel(const float* __restrict__ W1, const float* __restrict__ W2) {
    int i = (blockIdx.x * blockDim.x + threadIdx.x) * 4;
    const float* W = (i < DIMV * DIMV) ? W1 : W2;
    int j = i & (DIMV * DIMV - 1);
    float4 v = *(const float4*)&W[j];
    half2* dst = (half2*)&g_wh[i];
    dst[0] = __floats2half2_rn(v.x, v.y);
    dst[1] = __floats2half2_rn(v.z, v.w);
}

// ---------------- kernel 1: h = x @ [W1|W2] via HMMA, BOTH layers per block ----------------
// grid: ceil(n/128), block 512 (16 warps). Tile M=128, N=128 per layer, K chunks of 32.
// Register-prefetch pipeline: chunk k+1 LDGs issue before chunk-k MMAs.
#define XH_LD 40      // 32 + 8 pad
#define WH_LD 136     // 128 + 8 pad
#define CS_LD 68
#define XH_BYTES (128 * XH_LD * 2)          // 10240
#define WH_BYTES (32 * WH_LD * 2)           // 8704 per layer
#define GEMM_SMEM 34816                     // Cs 128*68*4 aliases (> Xh+2*Wh = 27648)
__global__ __launch_bounds__(512) void gemm_hmma(const float* __restrict__ x,
                                                 const float* __restrict__ as1,
                                                 const float* __restrict__ ad1,
                                                 const float* __restrict__ as2,
                                                 const float* __restrict__ ad2, int n) {
    __shared__ __align__(16) char buf[GEMM_SMEM];
    half (*Xh)[XH_LD] = (half(*)[XH_LD])buf;                         // 128 x 32 half
    half (*Wh0)[WH_LD] = (half(*)[WH_LD])(buf + XH_BYTES);           // 32 x 128 half
    half (*Wh1)[WH_LD] = (half(*)[WH_LD])(buf + XH_BYTES + WH_BYTES);
    float (*Cs)[CS_LD] = (float(*)[CS_LD])buf;                       // 128 x 68 float (aliases)

    int tid = threadIdx.x;
    int rowBase = blockIdx.x * 128;
    int warp = tid >> 5;
    int wr = warp & 7;    // 8 row groups of 16
    int wc = warp >> 3;   // 2 col groups of 64

    wmma::fragment<wmma::accumulator, 16, 16, 16, float> acc[2][4];
#pragma unroll
    for (int l = 0; l < 2; l++)
#pragma unroll
        for (int j = 0; j < 4; j++) wmma::fill_fragment(acc[l][j], 0.f);

    int row4 = tid >> 2, q4 = tid & 3;          // X: 4 threads/row of 128, 8 cols each
    int wlay = tid >> 8;                        // W: threads 0-255 -> layer0, 256-511 -> layer1
    int wt = tid & 255;
    int wrow = wt >> 3, wq8 = wt & 7;           // 8 threads/row of 32, 16 cols each
    half (*WhT)[WH_LD] = wlay ? Wh1 : Wh0;
    const half* WlT = &g_wh[wlay * DIMV * DIMV];
    int grow = rowBase + row4;

    // prologue: load chunk 0 into regs, store, sync
    float4 v0 = make_float4(0.f, 0.f, 0.f, 0.f), v1 = v0;
    if (grow < n) {
        v0 = *(const float4*)&x[grow * DIMV + q4 * 8];
        v1 = *(const float4*)&x[grow * DIMV + q4 * 8 + 4];
    }
    uint4 wv0 = *(const uint4*)&WlT[wrow * DIMV + wq8 * 16];
    uint4 wv1 = *(const uint4*)&WlT[wrow * DIMV + wq8 * 16 + 8];
    {
        half2* dst = (half2*)&Xh[row4][q4 * 8];
        dst[0] = __floats2half2_rn(v0.x, v0.y);
        dst[1] = __floats2half2_rn(v0.z, v0.w);
        dst[2] = __floats2half2_rn(v1.x, v1.y);
        dst[3] = __floats2half2_rn(v1.z, v1.w);
        uint4* wd = (uint4*)&WhT[wrow][wq8 * 16];
        wd[0] = wv0;
        wd[1] = wv1;
    }
    __syncthreads();

#pragma unroll
    for (int kc = 0; kc < 4; kc++) {
        // prefetch chunk kc+1 into registers (overlaps with MMA below)
        if (kc < 3) {
            int k0 = (kc + 1) * 32;
            v0 = make_float4(0.f, 0.f, 0.f, 0.f); v1 = v0;
            if (grow < n) {
                v0 = *(const float4*)&x[grow * DIMV + k0 + q4 * 8];
                v1 = *(const float4*)&x[grow * DIMV + k0 + q4 * 8 + 4];
            }
            wv0 = *(const uint4*)&WlT[(k0 + wrow) * DIMV + wq8 * 16];
            wv1 = *(const uint4*)&WlT[(k0 + wrow) * DIMV + wq8 * 16 + 8];
        }
        // MMA on current smem
#pragma unroll
        for (int kk = 0; kk < 2; kk++) {
            wmma::fragment<wmma::matrix_a, 16, 16, 16, half, wmma::row_major> fa;
            wmma::load_matrix_sync(fa, &Xh[wr * 16][kk * 16], XH_LD);
#pragma unroll
            for (int j = 0; j < 4; j++) {
                wmma::fragment<wmma::matrix_b, 16, 16, 16, half, wmma::row_major> fb0;
                wmma::load_matrix_sync(fb0, &Wh0[kk * 16][wc * 64 + j * 16], WH_LD);
                wmma::mma_sync(acc[0][j], fa, fb0, acc[0][j]);
                wmma::fragment<wmma::matrix_b, 16, 16, 16, half, wmma::row_major> fb1;
                wmma::load_matrix_sync(fb1, &Wh1[kk * 16][wc * 64 + j * 16], WH_LD);
                wmma::mma_sync(acc[1][j], fa, fb1, acc[1][j]);
            }
        }
        __syncthreads();
        if (kc < 3) {
            half2* dst = (half2*)&Xh[row4][q4 * 8];
            dst[0] = __floats2half2_rn(v0.x, v0.y);
            dst[1] = __floats2half2_rn(v0.z, v0.w);
            dst[2] = __floats2half2_rn(v1.x, v1.y);
            dst[3] = __floats2half2_rn(v1.z, v1.w);
            uint4* wd = (uint4*)&WhT[wrow][wq8 * 16];
            wd[0] = wv0;
            wd[1] = wv1;
            __syncthreads();
        }
    }

    // Four-phase epilogue: layer l, phase ph covers channels [64ph, 64ph+64) = heads 2ph, 2ph+1.
#pragma unroll
    for (int l = 0; l < 2; l++) {
#pragma unroll
        for (int ph = 0; ph < 2; ph++) {
            if (wc == ph) {
#pragma unroll
                for (int j = 0; j < 4; j++)
                    wmma::store_matrix_sync(&Cs[wr * 16][j * 16], acc[l][j], CS_LD, wmma::mem_row_major);
            }
            __syncthreads();
            if (grow < n) {
#pragma unroll
                for (int mm = 0; mm < 4; mm++) {
                    int relc = q4 * 16 + mm * 4;
                    float c0 = Cs[row4][relc + 0];
                    float c1 = Cs[row4][relc + 1];
                    float c2 = Cs[row4][relc + 2];
                    float c3 = Cs[row4][relc + 3];
                    int m = (ph * 64 + relc) >> 2;               // global pair-pair index
                    uint2 w2;
                    w2.x = f2bf2(c0, c1);
                    w2.y = f2bf2(c2, c3);
                    *(uint2*)&g_hb[grow * 128 + 4 * m + 2 * l] = w2;
                }
                if (q4 < 2) {
                    int hh = ph * 2 + q4;
                    const float* as = (l == 0) ? as1 : as2;
                    const float* ad = (l == 0) ? ad1 : ad2;
                    float ps = 0.f, pd = 0.f;
#pragma unroll
                    for (int c = 0; c < 32; c += 4) {
                        float4 h4 = *(const float4*)&Cs[row4][q4 * 32 + c];
                        float4 a4 = *(const float4*)&as[hh * CH + c];
                        float4 d4 = *(const float4*)&ad[hh * CH + c];
                        ps += h4.x * a4.x + h4.y * a4.y + h4.z * a4.z + h4.w * a4.w;
                        pd += h4.x * d4.x + h4.y * d4.y + h4.z * d4.z + h4.w * d4.w;
                    }
                    g_srcv[grow * 8 + hh * 2 + l] = ps;
                    g_dstv[grow * 8 + hh * 2 + l] = pd;
                }
            }
            __syncthreads();
        }
    }
}

// ---------------- CSR build ----------------
__global__ void count_kernel(const int* __restrict__ ei, int E) {
    int e4 = blockIdx.x * blockDim.x + threadIdx.x;
    int base = e4 * 4;
    if (base + 4 <= E && (E & 3) == 0) {
        int4 d = *(const int4*)&ei[E + base];
        atomicAdd(&g_deg[d.x], 1);
        atomicAdd(&g_deg[d.y], 1);
        atomicAdd(&g_deg[d.z], 1);
        atomicAdd(&g_deg[d.w], 1);
    } else {
        for (int e = base; e < E && e < base + 4; e++) atomicAdd(&g_deg[ei[E + e]], 1);
    }
}

__global__ __launch_bounds__(256) void scanA_kernel(int n) {
    __shared__ int sm[8];
    int t = threadIdx.x;
    int i = blockIdx.x * 256 + t;
    int v = (i < n) ? g_deg[i] + 1 : 0;
#pragma unroll
    for (int off = 16; off; off >>= 1) v += __shfl_xor_sync(0xffffffffu, v, off);
    if ((t & 31) == 0) sm[t >> 5] = v;
    __syncthreads();
    if (t == 0) {
        int s = 0;
#pragma unroll
        for (int j = 0; j < 8; j++) s += sm[j];
        g_bsum[blockIdx.x] = s;
    }
}

__global__ __launch_bounds__(256) void scanC2_kernel(int nb, int n) {
    __shared__ int rlt[8], rall[8], wsum[8];
    int t = threadIdx.x, lane = t & 31, w = t >> 5;
    int bid = blockIdx.x;
    int bv = (t < nb) ? g_bsum[t] : 0;
    int blt = (t < bid) ? bv : 0;
    int ball = bv;
#pragma unroll
    for (int off = 16; off; off >>= 1) {
        blt += __shfl_xor_sync(0xffffffffu, blt, off);
        ball += __shfl_xor_sync(0xffffffffu, ball, off);
    }
    if (lane == 0) { rlt[w] = blt; rall[w] = ball; }
    __syncthreads();
    if (t == 0) {
        int a = 0, b = 0;
#pragma unroll
        for (int j = 0; j < 8; j++) { a += rlt[j]; b += rall[j]; }
        rlt[0] = a; rall[0] = b;
    }
    __syncthreads();
    int boff = rlt[0];
    if (bid == 0 && t == 0) g_off[n] = rall[0];
    int i = bid * 256 + t;
    int v = (i < n) ? g_deg[i] + 1 : 0;
    int x = v;
#pragma unroll
    for (int off = 1; off < 32; off <<= 1) {
        int u = __shfl_up_sync(0xffffffffu, x, off);
        if (lane >= off) x += u;
    }
    if (lane == 31) wsum[w] = x;
    __syncthreads();
    if (t == 0) {
        int acc = 0;
#pragma unroll
        for (int j = 0; j < 8; j++) { int tmp = wsum[j]; wsum[j] = acc; acc += tmp; }
    }
    __syncthreads();
    if (i < n) {
        int base = boff + wsum[w] + (x - v);
        g_off[i] = base;
        g_csr[base] = i;          // self-loop first
        g_cursor[i] = base + 1;
        g_deg[i] = 0;             // re-zero for next replay (deterministic)
    }
}

__global__ void scatter_kernel(const int* __restrict__ ei, int E) {
    int e4 = blockIdx.x * blockDim.x + threadIdx.x;
    int base = e4 * 4;
    if (base + 4 <= E && (E & 3) == 0) {
        int4 s = *(const int4*)&ei[base];
        int4 d = *(const int4*)&ei[E + base];
        g_csr[atomicAdd(&g_cursor[d.x], 1)] = s.x;
        g_csr[atomicAdd(&g_cursor[d.y], 1)] = s.y;
        g_csr[atomicAdd(&g_cursor[d.z], 1)] = s.z;
        g_csr[atomicAdd(&g_cursor[d.w], 1)] = s.w;
    } else {
        for (int e = base; e < E && e < base + 4; e++)
            g_csr[atomicAdd(&g_cursor[ei[E + e]], 1)] = ei[e];
    }
}

// ---------------- finalize helper: gate + residual + LN for one node (warp-collective) ----------------
__device__ __forceinline__ void finalize_node(
        int node, float4 o1, float4 o2, int lane,
        const float* __restrict__ x, const float* __restrict__ gW, const float* __restrict__ gb,
        const float* __restrict__ gamma, const float* __restrict__ beta, float* __restrict__ out) {
    int c0 = lane * 4;
    float g0 = 0.f, g1 = 0.f;
    {
        const float* w1r = &gW[c0 * 2];
        const float* w2r = &gW[(128 + c0) * 2];
        g0 += o1.x * w1r[0] + o1.y * w1r[2] + o1.z * w1r[4] + o1.w * w1r[6];
        g1 += o1.x * w1r[1] + o1.y * w1r[3] + o1.z * w1r[5] + o1.w * w1r[7];
        g0 += o2.x * w2r[0] + o2.y * w2r[2] + o2.z * w2r[4] + o2.w * w2r[6];
        g1 += o2.x * w2r[1] + o2.y * w2r[3] + o2.z * w2r[5] + o2.w * w2r[7];
    }
#pragma unroll
    for (int off = 16; off; off >>= 1) {
        g0 += __shfl_xor_sync(0xffffffffu, g0, off);
        g1 += __shfl_xor_sync(0xffffffffu, g1, off);
    }
    g0 += gb[0]; g1 += gb[1];
    float mx = fmaxf(g0, g1);
    float e0 = __expf(g0 - mx), e1 = __expf(g1 - mx);
    float inv_se = 1.f / (e0 + e1);
    float w0 = e0 * inv_se, w1 = e1 * inv_se;

    float4 xv = *(const float4*)&x[node * DIMV + c0];
    float4 y;
    y.x = xv.x + w0 * o1.x + w1 * o2.x;
    y.y = xv.y + w0 * o1.y + w1 * o2.y;
    y.z = xv.z + w0 * o1.z + w1 * o2.z;
    y.w = xv.w + w0 * o1.w + w1 * o2.w;
    float sum = y.x + y.y + y.z + y.w;
    float sq  = y.x * y.x + y.y * y.y + y.z * y.z + y.w * y.w;
#pragma unroll
    for (int off = 16; off; off >>= 1) {
        sum += __shfl_xor_sync(0xffffffffu, sum, off);
        sq  += __shfl_xor_sync(0xffffffffu, sq, off);
    }
    float mu = sum * (1.f / DIMV);
    float var = sq * (1.f / DIMV) - mu * mu;
    float inv = rsqrtf(var + LN_EPS);
    float4 gm = *(const float4*)&gamma[c0];
    float4 bt = *(const float4*)&beta[c0];
    float4 r;
    r.x = (y.x - mu) * inv * gm.x + bt.x;
    r.y = (y.y - mu) * inv * gm.y + bt.y;
    r.z = (y.z - mu) * inv * gm.z + bt.z;
    r.w = (y.w - mu) * inv * gm.w + bt.w;
    *(float4*)&out[node * DIMV + c0] = r;
}

// ---------------- kernel 3: aggregation, TWO nodes per warp (interleaved chains) ----------------
__global__ __launch_bounds__(256) void agg_finalize_kernel(
        const float* __restrict__ x,
        const float* __restrict__ b1, const float* __restrict__ b2,
        const float* __restrict__ gW, const float* __restrict__ gb,
        const float* __restrict__ gamma, const float* __restrict__ beta,
        float* __restrict__ out, int n) {
    int wid = (blockIdx.x * blockDim.x + threadIdx.x) >> 5;
    int nodeA = wid * 2;
    if (nodeA >= n) return;
    int nodeB = nodeA + 1;
    bool hasB = nodeB < n;
    int lane = threadIdx.x & 31;
    int head = lane >> 3;

    float2 edA = *(const float2*)&g_dstv[nodeA * 8 + head * 2];
    float2 edB = hasB ? *(const float2*)&g_dstv[nodeB * 8 + head * 2] : edA;
    int begA = g_off[nodeA];
    int itA = g_off[nodeA + 1] - begA;
    int begB = hasB ? g_off[nodeB] : begA;
    int itB = hasB ? (g_off[nodeB + 1] - begB) : 0;
    int iters = itA > itB ? itA : itB;

    ull nA1a = 0ull, nA1b = 0ull, nA2a = 0ull, nA2b = 0ull;
    ull nB1a = 0ull, nB1b = 0ull, nB2a = 0ull, nB2b = 0ull;
    float denA1 = 0.f, denA2 = 0.f, denB1 = 0.f, denB2 = 0.f;

    // preload first indices (self-loop guarantees >=1 edge for valid nodes)
    int sA = __ldg(&g_csr[begA]);
    int sB = hasB ? __ldg(&g_csr[begB]) : sA;

    for (int it = 0; it < iters; it++) {
        int csA = sA, csB = sB;
        // prefetch next indices (off both chains' critical paths)
        if (it + 1 < itA) sA = __ldg(&g_csr[begA + it + 1]);
        if (it + 1 < itB) sB = __ldg(&g_csr[begB + it + 1]);
        // two independent gather chains
        uint4 qA = *(const uint4*)&g_hb[csA * 128 + lane * 4];
        uint4 qB = *(const uint4*)&g_hb[csB * 128 + lane * 4];
        float2 eA = *(const float2*)&g_srcv[csA * 8 + head * 2];
        float2 eB = *(const float2*)&g_srcv[csB * 8 + head * 2];
        bool vA = it < itA;
        bool vB = it < itB;
        float pA1 = vA ? __expf(lrelu(eA.x + edA.x)) : 0.f;
        float pA2 = vA ? __expf(lrelu(eA.y + edA.y)) : 0.f;
        float pB1 = vB ? __expf(lrelu(eB.x + edB.x)) : 0.f;
        float pB2 = vB ? __expf(lrelu(eB.y + edB.y)) : 0.f;
        denA1 += pA1; denA2 += pA2; denB1 += pB1; denB2 += pB2;
        ull kA1 = pack2(pA1, pA1), kA2 = pack2(pA2, pA2);
        ull kB1 = pack2(pB1, pB1), kB2 = pack2(pB2, pB2);
        ffma2(nA1a, kA1, bf2f2(qA.x));
        ffma2(nA1b, kA1, bf2f2(qA.y));
        ffma2(nA2a, kA2, bf2f2(qA.z));
        ffma2(nA2b, kA2, bf2f2(qA.w));
        ffma2(nB1a, kB1, bf2f2(qB.x));
        ffma2(nB1b, kB1, bf2f2(qB.y));
        ffma2(nB2a, kB2, bf2f2(qB.z));
        ffma2(nB2b, kB2, bf2f2(qB.w));
    }

    int c0 = lane * 4;
    float4 bb1 = *(const float4*)&b1[c0];
    float4 bb2 = *(const float4*)&b2[c0];
    {
        float inv1 = 1.f / denA1, inv2 = 1.f / denA2;
        float4 n1, n2, o1, o2;
        unpack2(nA1a, n1.x, n1.y); unpack2(nA1b, n1.z, n1.w);
        unpack2(nA2a, n2.x, n2.y); unpack2(nA2b, n2.z, n2.w);
        o1.x = n1.x * inv1 + bb1.x; o1.y = n1.y * inv1 + bb1.y;
        o1.z = n1.z * inv1 + bb1.z; o1.w = n1.w * inv1 + bb1.w;
        o2.x = n2.x * inv2 + bb2.x; o2.y = n2.y * inv2 + bb2.y;
        o2.z = n2.z * inv2 + bb2.z; o2.w = n2.w * inv2 + bb2.w;
        finalize_node(nodeA, o1, o2, lane, x, gW, gb, gamma, beta, out);
    }
    if (hasB) {
        float inv1 = 1.f / denB1, inv2 = 1.f / denB2;
        float4 n1, n2, o1, o2;
        unpack2(nB1a, n1.x, n1.y); unpack2(nB1b, n1.z, n1.w);
        unpack2(nB2a, n2.x, n2.y); unpack2(nB2b, n2.z, n2.w);
        o1.x = n1.x * inv1 + bb1.x; o1.y = n1.y * inv1 + bb1.y;
        o1.z = n1.z * inv1 + bb1.z; o1.w = n1.w * inv1 + bb1.w;
        o2.x = n2.x * inv2 + bb2.x; o2.y = n2.y * inv2 + bb2.y;
        o2.z = n2.z * inv2 + bb2.z; o2.w = n2.w * inv2 + bb2.w;
        finalize_node(nodeB, o1, o2, lane, x, gW, gb, gamma, beta, out);
    }
}

// ---------------- stream/event infrastructure (created once at load) ----------------
static cudaStream_t g_s1;
static cudaEvent_t g_evFork, g_evJoin;
static int g_stream_init = []() {
    cudaStreamCreateWithFlags(&g_s1, cudaStreamNonBlocking);
    cudaEventCreateWithFlags(&g_evFork, cudaEventDisableTiming);
    cudaEventCreateWithFlags(&g_evJoin, cudaEventDisableTiming);
    return 0;
}();

// ---------------- launch ----------------
extern "C" void kernel_launch(void* const* d_in, const int* in_sizes, int n_in,
                              void* d_out, int out_size) {
    const float* x   = (const float*)d_in[0];
    const int*   ei  = (const int*)d_in[1];
    const float* W1  = (const float*)d_in[2];
    const float* b1  = (const float*)d_in[3];
    const float* as1 = (const float*)d_in[4];
    const float* ad1 = (const float*)d_in[5];
    const float* W2  = (const float*)d_in[6];
    const float* b2  = (const float*)d_in[7];
    const float* as2 = (const float*)d_in[8];
    const float* ad2 = (const float*)d_in[9];
    const float* gW  = (const float*)d_in[10];
    const float* gb  = (const float*)d_in[11];
    const float* gam = (const float*)d_in[12];
    const float* bet = (const float*)d_in[13];
    float* out = (float*)d_out;

    int n = in_sizes[0] / DIMV;       // nodes
    int E = in_sizes[1] / 2;          // edges (before self-loops)
    int nb = (n + 255) / 256;         // scan blocks (<= 256)
    int e4 = (E + 3) / 4;             // 4-edge work items
    int nwarps = (n + 1) / 2;         // 2 nodes per warp

    // Fork: CSR build (depends only on ei) on side stream
    cudaEventRecord(g_evFork, 0);
    cudaStreamWaitEvent(g_s1, g_evFork, 0);

    // Branch A (stream 0): W -> half, then h = x @ [W1|W2] (both layers per block) + fused logits
    wconv_kernel<<<32, 256>>>(W1, W2);
    gemm_hmma<<<(n + 127) / 128, 512>>>(x, as1, ad1, as2, ad2, n);

    // Branch B (stream s1): CSR build (dst-grouped)
    count_kernel<<<(e4 + 255) / 256, 256, 0, g_s1>>>(ei, E);
    scanA_kernel<<<nb, 256, 0, g_s1>>>(n);
    scanC2_kernel<<<nb, 256, 0, g_s1>>>(nb, n);
    scatter_kernel<<<(e4 + 255) / 256, 256, 0, g_s1>>>(ei, E);

    // Join
    cudaEventRecord(g_evJoin, g_s1);
    cudaStreamWaitEvent(0, g_evJoin, 0);

    // Aggregation (2 nodes/warp, interleaved chains) + gate + residual + LN
    agg_finalize_kernel<<<(nwarps * 32 + 255) / 256, 256>>>(x, b1, b2, gW, gb, gam, bet, out, n);
}

// round 17
// speedup vs baseline: 1.2399x; 1.2399x over previous
#include <cuda_runtime.h>
#include <cuda_fp16.h>
#include <cuda_bf16.h>
#include <mma.h>
#include <cstdint>

using namespace nvcuda;

// Problem constants (fixed by the reference)
#define MAXN 50000
#define DIMV 128
#define HEADS 4
#define CH 32
#define MAXE 800000
#define LRELU_SLOPE 0.2f
#define LN_EPS 1e-5f

typedef unsigned long long ull;

// ---------------- scratch (device globals; no allocation allowed) ----------------
// g_hb layout (interleaved): [N][128] words, word = 2 bf16.
// For channel-pair p (0..63), layer l: word = (p>>1)*4 + l*2 + (p&1)
// => lane's uint4 at word lane*4 = {h1 pairs 2lane,2lane+1, h2 pairs 2lane,2lane+1}
__device__ unsigned int g_hb[MAXN * 128];
__device__ half  g_wh[2 * DIMV * DIMV];     // W1|W2 pre-converted to half, row-major [k][n]
__device__ float g_srcv[MAXN * 8];          // [node][head][layer]
__device__ float g_dstv[MAXN * 8];          // same layout
__device__ int   g_deg[MAXN];               // edge in-degree (zero-init; self-loop via +1)
__device__ int   g_off[MAXN + 1];           // CSR offsets
__device__ int   g_cursor[MAXN];            // scatter cursors
__device__ int   g_csr[MAXE + MAXN + 64];   // CSR src indices (grouped by dst) + pad
__device__ int   g_bsum[256];               // per-block degree sums

__device__ __forceinline__ float lrelu(float v) { return v > 0.f ? v : LRELU_SLOPE * v; }

__device__ __forceinline__ ull pack2(float x, float y) {
    ull r;
    asm("mov.b64 %0, {%1, %2};" : "=l"(r) : "f"(x), "f"(y));
    return r;
}
__device__ __forceinline__ void unpack2(ull v, float& x, float& y) {
    asm("mov.b64 {%0, %1}, %2;" : "=f"(x), "=f"(y) : "l"(v));
}
__device__ __forceinline__ void ffma2(ull& d, ull a, ull b) {
    asm("fma.rn.f32x2 %0, %1, %2, %0;" : "+l"(d) : "l"(a), "l"(b));
}
__device__ __forceinline__ unsigned int f2bf2(float lo, float hi) {
    unsigned int r;
    asm("cvt.rn.bf16x2.f32 %0, %1, %2;" : "=r"(r) : "f"(hi), "f"(lo));
    return r;
}
// word of two bf16 -> packed f32x2 (exact: bf16->f32 is <<16)
__device__ __forceinline__ ull bf2f2(unsigned int w) {
    ull r;
    asm("mov.b64 %0, {%1, %2};" : "=l"(r) : "r"(w << 16), "r"(w & 0xffff0000u));
    return r;
}

// ---------------- kernel 0: pre-convert W1|W2 to half ----------------
__global__ void wconv_kernel(const float* __restrict__ W1, const float* __restrict__ W2) {
    int i = (blockIdx.x * blockDim.x + threadIdx.x) * 4;
    const float* W = (i < DIMV * DIMV) ? W1 : W2;
    int j = i & (DIMV * DIMV - 1);
    float4 v = *(const float4*)&W[j];
    half2* dst = (half2*)&g_wh[i];
    dst[0] = __floats2half2_rn(v.x, v.y);
    dst[1] = __floats2half2_rn(v.z, v.w);
}

// ---------------- kernel 1: h = x @ [W1|W2] via HMMA, BOTH layers per block ----------------
// grid: ceil(n/128), block 512 (16 warps). Tile M=128, N=128 per layer, K chunks of 32.
// x tile loaded/converted ONCE, used for both layers.
#define XH_LD 40      // 32 + 8 pad
#define WH_LD 136     // 128 + 8 pad
#define CS_LD 68
#define XH_BYTES (128 * XH_LD * 2)          // 10240
#define WH_BYTES (32 * WH_LD * 2)           // 8704 per layer
#define GEMM_SMEM 34816                     // Cs 128*68*4 aliases (> Xh+2*Wh = 27648)
__global__ __launch_bounds__(512) void gemm_hmma(const float* __restrict__ x,
                                                 const float* __restrict__ as1,
                                                 const float* __restrict__ ad1,
                                                 const float* __restrict__ as2,
                                                 const float* __restrict__ ad2, int n) {
    __shared__ __align__(16) char buf[GEMM_SMEM];
    half (*Xh)[XH_LD] = (half(*)[XH_LD])buf;                         // 128 x 32 half
    half (*Wh0)[WH_LD] = (half(*)[WH_LD])(buf + XH_BYTES);           // 32 x 128 half
    half (*Wh1)[WH_LD] = (half(*)[WH_LD])(buf + XH_BYTES + WH_BYTES);
    float (*Cs)[CS_LD] = (float(*)[CS_LD])buf;                       // 128 x 68 float (aliases)

    int tid = threadIdx.x;
    int rowBase = blockIdx.x * 128;
    int warp = tid >> 5;
    int wr = warp & 7;    // 8 row groups of 16
    int wc = warp >> 3;   // 2 col groups of 64

    wmma::fragment<wmma::accumulator, 16, 16, 16, float> acc[2][4];
#pragma unroll
    for (int l = 0; l < 2; l++)
#pragma unroll
        for (int j = 0; j < 4; j++) wmma::fill_fragment(acc[l][j], 0.f);

    int row4 = tid >> 2, q4 = tid & 3;          // X: 4 threads/row of 128, 8 cols each
    int wlay = tid >> 8;                        // W: threads 0-255 -> layer0, 256-511 -> layer1
    int wt = tid & 255;
    int wrow = wt >> 3, wq8 = wt & 7;           // 8 threads/row of 32, 16 cols each
    half (*WhT)[WH_LD] = wlay ? Wh1 : Wh0;
    const half* WlT = &g_wh[wlay * DIMV * DIMV];

    for (int k0 = 0; k0 < DIMV; k0 += 32) {
        // load X tile 128x32 (fp32 -> half): 8 floats per thread
        {
            int grow = rowBase + row4;
            float4 v0 = make_float4(0.f, 0.f, 0.f, 0.f);
            float4 v1 = v0;
            if (grow < n) {
                v0 = *(const float4*)&x[grow * DIMV + k0 + q4 * 8];
                v1 = *(const float4*)&x[grow * DIMV + k0 + q4 * 8 + 4];
            }
            half2* dst = (half2*)&Xh[row4][q4 * 8];
            dst[0] = __floats2half2_rn(v0.x, v0.y);
            dst[1] = __floats2half2_rn(v0.z, v0.w);
            dst[2] = __floats2half2_rn(v1.x, v1.y);
            dst[3] = __floats2half2_rn(v1.z, v1.w);
        }
        // load W tiles 32x128 (half), one layer per thread-half: 16 halves = 2 x uint4
        {
            const uint4* src = (const uint4*)&WlT[(k0 + wrow) * DIMV + wq8 * 16];
            uint4* dst = (uint4*)&WhT[wrow][wq8 * 16];
            dst[0] = src[0];
            dst[1] = src[1];
        }
        __syncthreads();
#pragma unroll
        for (int kk = 0; kk < 2; kk++) {
            wmma::fragment<wmma::matrix_a, 16, 16, 16, half, wmma::row_major> fa;
            wmma::load_matrix_sync(fa, &Xh[wr * 16][kk * 16], XH_LD);
#pragma unroll
            for (int j = 0; j < 4; j++) {
                wmma::fragment<wmma::matrix_b, 16, 16, 16, half, wmma::row_major> fb0;
                wmma::load_matrix_sync(fb0, &Wh0[kk * 16][wc * 64 + j * 16], WH_LD);
                wmma::mma_sync(acc[0][j], fa, fb0, acc[0][j]);
                wmma::fragment<wmma::matrix_b, 16, 16, 16, half, wmma::row_major> fb1;
                wmma::load_matrix_sync(fb1, &Wh1[kk * 16][wc * 64 + j * 16], WH_LD);
                wmma::mma_sync(acc[1][j], fa, fb1, acc[1][j]);
            }
        }
        __syncthreads();
    }

    // Four-phase epilogue: layer l, phase ph covers channels [64ph, 64ph+64) = heads 2ph, 2ph+1.
    int grow = rowBase + row4;
#pragma unroll
    for (int l = 0; l < 2; l++) {
#pragma unroll
        for (int ph = 0; ph < 2; ph++) {
            if (wc == ph) {
#pragma unroll
                for (int j = 0; j < 4; j++)
                    wmma::store_matrix_sync(&Cs[wr * 16][j * 16], acc[l][j], CS_LD, wmma::mem_row_major);
            }
            __syncthreads();
            if (grow < n) {
#pragma unroll
                for (int mm = 0; mm < 4; mm++) {
                    int relc = q4 * 16 + mm * 4;
                    float c0 = Cs[row4][relc + 0];
                    float c1 = Cs[row4][relc + 1];
                    float c2 = Cs[row4][relc + 2];
                    float c3 = Cs[row4][relc + 3];
                    int m = (ph * 64 + relc) >> 2;               // global pair-pair index
                    uint2 w2;
                    w2.x = f2bf2(c0, c1);
                    w2.y = f2bf2(c2, c3);
                    *(uint2*)&g_hb[grow * 128 + 4 * m + 2 * l] = w2;
                }
                if (q4 < 2) {
                    int hh = ph * 2 + q4;
                    const float* as = (l == 0) ? as1 : as2;
                    const float* ad = (l == 0) ? ad1 : ad2;
                    float ps = 0.f, pd = 0.f;
#pragma unroll
                    for (int c = 0; c < 32; c += 4) {
                        float4 h4 = *(const float4*)&Cs[row4][q4 * 32 + c];
                        float4 a4 = *(const float4*)&as[hh * CH + c];
                        float4 d4 = *(const float4*)&ad[hh * CH + c];
                        ps += h4.x * a4.x + h4.y * a4.y + h4.z * a4.z + h4.w * a4.w;
                        pd += h4.x * d4.x + h4.y * d4.y + h4.z * d4.z + h4.w * d4.w;
                    }
                    g_srcv[grow * 8 + hh * 2 + l] = ps;
                    g_dstv[grow * 8 + hh * 2 + l] = pd;
                }
            }
            __syncthreads();
        }
    }
}

// ---------------- CSR build ----------------
__global__ void count_kernel(const int* __restrict__ ei, int E) {
    int e4 = blockIdx.x * blockDim.x + threadIdx.x;
    int base = e4 * 4;
    if (base + 4 <= E && (E & 3) == 0) {
        int4 d = *(const int4*)&ei[E + base];
        atomicAdd(&g_deg[d.x], 1);
        atomicAdd(&g_deg[d.y], 1);
        atomicAdd(&g_deg[d.z], 1);
        atomicAdd(&g_deg[d.w], 1);
    } else {
        for (int e = base; e < E && e < base + 4; e++) atomicAdd(&g_deg[ei[E + e]], 1);
    }
}

__global__ __launch_bounds__(256) void scanA_kernel(int n) {
    __shared__ int sm[8];
    int t = threadIdx.x;
    int i = blockIdx.x * 256 + t;
    int v = (i < n) ? g_deg[i] + 1 : 0;
#pragma unroll
    for (int off = 16; off; off >>= 1) v += __shfl_xor_sync(0xffffffffu, v, off);
    if ((t & 31) == 0) sm[t >> 5] = v;
    __syncthreads();
    if (t == 0) {
        int s = 0;
#pragma unroll
        for (int j = 0; j < 8; j++) s += sm[j];
        g_bsum[blockIdx.x] = s;
    }
}

__global__ __launch_bounds__(256) void scanC2_kernel(int nb, int n) {
    __shared__ int rlt[8], rall[8], wsum[8];
    int t = threadIdx.x, lane = t & 31, w = t >> 5;
    int bid = blockIdx.x;
    int bv = (t < nb) ? g_bsum[t] : 0;
    int blt = (t < bid) ? bv : 0;
    int ball = bv;
#pragma unroll
    for (int off = 16; off; off >>= 1) {
        blt += __shfl_xor_sync(0xffffffffu, blt, off);
        ball += __shfl_xor_sync(0xffffffffu, ball, off);
    }
    if (lane == 0) { rlt[w] = blt; rall[w] = ball; }
    __syncthreads();
    if (t == 0) {
        int a = 0, b = 0;
#pragma unroll
        for (int j = 0; j < 8; j++) { a += rlt[j]; b += rall[j]; }
        rlt[0] = a; rall[0] = b;
    }
    __syncthreads();
    int boff = rlt[0];
    if (bid == 0 && t == 0) g_off[n] = rall[0];
    int i = bid * 256 + t;
    int v = (i < n) ? g_deg[i] + 1 : 0;
    int x = v;
#pragma unroll
    for (int off = 1; off < 32; off <<= 1) {
        int u = __shfl_up_sync(0xffffffffu, x, off);
        if (lane >= off) x += u;
    }
    if (lane == 31) wsum[w] = x;
    __syncthreads();
    if (t == 0) {
        int acc = 0;
#pragma unroll
        for (int j = 0; j < 8; j++) { int tmp = wsum[j]; wsum[j] = acc; acc += tmp; }
    }
    __syncthreads();
    if (i < n) {
        int base = boff + wsum[w] + (x - v);
        g_off[i] = base;
        g_csr[base] = i;          // self-loop first
        g_cursor[i] = base + 1;
        g_deg[i] = 0;             // re-zero for next replay (deterministic)
    }
}

__global__ void scatter_kernel(const int* __restrict__ ei, int E) {
    int e4 = blockIdx.x * blockDim.x + threadIdx.x;
    int base = e4 * 4;
    if (base + 4 <= E && (E & 3) == 0) {
        int4 s = *(const int4*)&ei[base];
        int4 d = *(const int4*)&ei[E + base];
        g_csr[atomicAdd(&g_cursor[d.x], 1)] = s.x;
        g_csr[atomicAdd(&g_cursor[d.y], 1)] = s.y;
        g_csr[atomicAdd(&g_cursor[d.z], 1)] = s.z;
        g_csr[atomicAdd(&g_cursor[d.w], 1)] = s.w;
    } else {
        for (int e = base; e < E && e < base + 4; e++)
            g_csr[atomicAdd(&g_cursor[ei[E + e]], 1)] = ei[e];
    }
}

// ---------------- kernel 3: CSR aggregation + gate + residual + LN (warp per node) ----------------
__global__ __launch_bounds__(256) void agg_finalize_kernel(
        const float* __restrict__ x,
        const float* __restrict__ b1, const float* __restrict__ b2,
        const float* __restrict__ gW, const float* __restrict__ gb,
        const float* __restrict__ gamma, const float* __restrict__ beta,
        float* __restrict__ out, int n) {
    int node = (blockIdx.x * blockDim.x + threadIdx.x) >> 5;
    if (node >= n) return;
    int lane = threadIdx.x & 31;
    int head = lane >> 3;
    int c0 = lane * 4;

    float2 ed = *(const float2*)&g_dstv[node * 8 + head * 2];  // (ed1, ed2)
    int beg = g_off[node];
    int end = g_off[node + 1];

    ull num1a = 0ull, num1b = 0ull, num2a = 0ull, num2b = 0ull;
    float den1 = 0.f, den2 = 0.f;

#define AGG_STEP(e, q) {                                        \
        float p1 = __expf(lrelu((e).x + ed.x));                 \
        float p2 = __expf(lrelu((e).y + ed.y));                 \
        den1 += p1; den2 += p2;                                 \
        ull pa = pack2(p1, p1), pb = pack2(p2, p2);             \
        ffma2(num1a, pa, bf2f2((q).x));                         \
        ffma2(num1b, pa, bf2f2((q).y));                         \
        ffma2(num2a, pb, bf2f2((q).z));                         \
        ffma2(num2b, pb, bf2f2((q).w));                         \
    }

    int p = beg;
    for (; p + 4 <= end; p += 4) {
        // uniform-address index loads: independent, L1-broadcast, no SHFL chain
        int s0 = __ldg(&g_csr[p]);
        int s1 = __ldg(&g_csr[p + 1]);
        int s2 = __ldg(&g_csr[p + 2]);
        int s3 = __ldg(&g_csr[p + 3]);
        uint4 q0 = *(const uint4*)&g_hb[s0 * 128 + lane * 4];
        uint4 q1 = *(const uint4*)&g_hb[s1 * 128 + lane * 4];
        uint4 q2 = *(const uint4*)&g_hb[s2 * 128 + lane * 4];
        uint4 q3 = *(const uint4*)&g_hb[s3 * 128 + lane * 4];
        float2 e0 = *(const float2*)&g_srcv[s0 * 8 + head * 2];
        float2 e1 = *(const float2*)&g_srcv[s1 * 8 + head * 2];
        float2 e2 = *(const float2*)&g_srcv[s2 * 8 + head * 2];
        float2 e3 = *(const float2*)&g_srcv[s3 * 8 + head * 2];
        AGG_STEP(e0, q0)
        AGG_STEP(e1, q1)
        AGG_STEP(e2, q2)
        AGG_STEP(e3, q3)
    }
    for (; p < end; p++) {
        int s = __ldg(&g_csr[p]);
        uint4 q = *(const uint4*)&g_hb[s * 128 + lane * 4];
        float2 e = *(const float2*)&g_srcv[s * 8 + head * 2];
        AGG_STEP(e, q)
    }
#undef AGG_STEP

    float inv1 = 1.f / den1;
    float inv2 = 1.f / den2;
    float4 num1, num2;
    unpack2(num1a, num1.x, num1.y); unpack2(num1b, num1.z, num1.w);
    unpack2(num2a, num2.x, num2.y); unpack2(num2b, num2.z, num2.w);
    float4 bb1 = *(const float4*)&b1[c0];
    float4 bb2 = *(const float4*)&b2[c0];
    float4 o1, o2;
    o1.x = num1.x * inv1 + bb1.x; o1.y = num1.y * inv1 + bb1.y;
    o1.z = num1.z * inv1 + bb1.z; o1.w = num1.w * inv1 + bb1.w;
    o2.x = num2.x * inv2 + bb2.x; o2.y = num2.y * inv2 + bb2.y;
    o2.z = num2.z * inv2 + bb2.z; o2.w = num2.w * inv2 + bb2.w;

    float g0 = 0.f, g1 = 0.f;
    {
        const float* w1r = &gW[c0 * 2];
        const float* w2r = &gW[(128 + c0) * 2];
        g0 += o1.x * w1r[0] + o1.y * w1r[2] + o1.z * w1r[4] + o1.w * w1r[6];
        g1 += o1.x * w1r[1] + o1.y * w1r[3] + o1.z * w1r[5] + o1.w * w1r[7];
        g0 += o2.x * w2r[0] + o2.y * w2r[2] + o2.z * w2r[4] + o2.w * w2r[6];
        g1 += o2.x * w2r[1] + o2.y * w2r[3] + o2.z * w2r[5] + o2.w * w2r[7];
    }
#pragma unroll
    for (int off = 16; off; off >>= 1) {
        g0 += __shfl_xor_sync(0xffffffffu, g0, off);
        g1 += __shfl_xor_sync(0xffffffffu, g1, off);
    }
    g0 += gb[0]; g1 += gb[1];
    float mx = fmaxf(g0, g1);
    float e0 = __expf(g0 - mx), e1 = __expf(g1 - mx);
    float inv_se = 1.f / (e0 + e1);
    float w0 = e0 * inv_se, w1 = e1 * inv_se;

    float4 xv = *(const float4*)&x[node * DIMV + c0];
    float4 y;
    y.x = xv.x + w0 * o1.x + w1 * o2.x;
    y.y = xv.y + w0 * o1.y + w1 * o2.y;
    y.z = xv.z + w0 * o1.z + w1 * o2.z;
    y.w = xv.w + w0 * o1.w + w1 * o2.w;
    float sum = y.x + y.y + y.z + y.w;
    float sq  = y.x * y.x + y.y * y.y + y.z * y.z + y.w * y.w;
#pragma unroll
    for (int off = 16; off; off >>= 1) {
        sum += __shfl_xor_sync(0xffffffffu, sum, off);
        sq  += __shfl_xor_sync(0xffffffffu, sq, off);
    }
    float mu = sum * (1.f / DIMV);
    float var = sq * (1.f / DIMV) - mu * mu;
    float inv = rsqrtf(var + LN_EPS);
    float4 gm = *(const float4*)&gamma[c0];
    float4 bt = *(const float4*)&beta[c0];
    float4 r;
    r.x = (y.x - mu) * inv * gm.x + bt.x;
    r.y = (y.y - mu) * inv * gm.y + bt.y;
    r.z = (y.z - mu) * inv * gm.z + bt.z;
    r.w = (y.w - mu) * inv * gm.w + bt.w;
    *(float4*)&out[node * DIMV + c0] = r;
}

// ---------------- stream/event infrastructure (created once at load) ----------------
static cudaStream_t g_s1;
static cudaEvent_t g_evFork, g_evJoin;
static int g_stream_init = []() {
    cudaStreamCreateWithFlags(&g_s1, cudaStreamNonBlocking);
    cudaEventCreateWithFlags(&g_evFork, cudaEventDisableTiming);
    cudaEventCreateWithFlags(&g_evJoin, cudaEventDisableTiming);
    return 0;
}();

// ---------------- launch ----------------
extern "C" void kernel_launch(void* const* d_in, const int* in_sizes, int n_in,
                              void* d_out, int out_size) {
    const float* x   = (const float*)d_in[0];
    const int*   ei  = (const int*)d_in[1];
    const float* W1  = (const float*)d_in[2];
    const float* b1  = (const float*)d_in[3];
    const float* as1 = (const float*)d_in[4];
    const float* ad1 = (const float*)d_in[5];
    const float* W2  = (const float*)d_in[6];
    const float* b2  = (const float*)d_in[7];
    const float* as2 = (const float*)d_in[8];
    const float* ad2 = (const float*)d_in[9];
    const float* gW  = (const float*)d_in[10];
    const float* gb  = (const float*)d_in[11];
    const float* gam = (const float*)d_in[12];
    const float* bet = (const float*)d_in[13];
    float* out = (float*)d_out;

    int n = in_sizes[0] / DIMV;       // nodes
    int E = in_sizes[1] / 2;          // edges (before self-loops)
    int nb = (n + 255) / 256;         // scan blocks (<= 256)
    int e4 = (E + 3) / 4;             // 4-edge work items

    // Fork: CSR build (depends only on ei) on side stream
    cudaEventRecord(g_evFork, 0);
    cudaStreamWaitEvent(g_s1, g_evFork, 0);

    // Branch A (stream 0): W -> half, then h = x @ [W1|W2] (both layers per block) + fused logits
    wconv_kernel<<<32, 256>>>(W1, W2);
    gemm_hmma<<<(n + 127) / 128, 512>>>(x, as1, ad1, as2, ad2, n);

    // Branch B (stream s1): CSR build (dst-grouped)
    count_kernel<<<(e4 + 255) / 256, 256, 0, g_s1>>>(ei, E);
    scanA_kernel<<<nb, 256, 0, g_s1>>>(n);
    scanC2_kernel<<<nb, 256, 0, g_s1>>>(nb, n);
    scatter_kernel<<<(e4 + 255) / 256, 256, 0, g_s1>>>(ei, E);

    // Join
    cudaEventRecord(g_evJoin, g_s1);
    cudaStreamWaitEvent(0, g_evJoin, 0);

    // Aggregation + gate + residual + LN
    agg_finalize_kernel<<<(n * 32 + 255) / 256, 256>>>(x, b1, b2, gW, gb, gam, bet, out, n);
}